// round 3
// baseline (speedup 1.0000x reference)
#include <cuda_runtime.h>
#include <cuda_bf16.h>

// Elementwise: y = (x + 1) * 2 / 3; if (y > 0) y -= 5;
// 8192*8192 fp32 = 67,108,864 elements (2^24 float4s). HBM-streaming.
//
// Geometry: 1024 blocks x 256 threads = 2^18 threads (single wave, ~7 blocks/SM).
// Each loop iteration: 4 independent LDG.128 front-batched (MLP_p1=4),
// 16 iterations per thread, exact divisibility -> no bounds checks.
// Default cache ops (R1 showed .cs/.stcs hurt DRAM utilization).

__device__ __forceinline__ float4 transform4(float4 v) {
    const float c = 2.0f / 3.0f;   // (x+1)*2/3 == fma(x, 2/3, 2/3)
    float4 r;
    r.x = fmaf(v.x, c, c);
    r.y = fmaf(v.y, c, c);
    r.z = fmaf(v.z, c, c);
    r.w = fmaf(v.w, c, c);
    if (r.x > 0.0f) r.x -= 5.0f;
    if (r.y > 0.0f) r.y -= 5.0f;
    if (r.z > 0.0f) r.z -= 5.0f;
    if (r.w > 0.0f) r.w -= 5.0f;
    return r;
}

// n4 must be divisible by 4 * gridDim.x * blockDim.x.
__global__ __launch_bounds__(256) void ew_loop4(const float4* __restrict__ x,
                                                float4* __restrict__ out,
                                                int n4) {
    const int T = gridDim.x * blockDim.x;       // total threads (2^18)
    int i = blockIdx.x * blockDim.x + threadIdx.x;
    const int step = 4 * T;
    for (; i < n4; i += step) {
        // 4 independent loads, front-batched
        float4 v0 = x[i + 0 * T];
        float4 v1 = x[i + 1 * T];
        float4 v2 = x[i + 2 * T];
        float4 v3 = x[i + 3 * T];
        out[i + 0 * T] = transform4(v0);
        out[i + 1 * T] = transform4(v1);
        out[i + 2 * T] = transform4(v2);
        out[i + 3 * T] = transform4(v3);
    }
}

// Fallback grid-stride for arbitrary sizes
__global__ __launch_bounds__(256) void ew_gs(const float4* __restrict__ x,
                                             float4* __restrict__ out, int n4) {
    int i = blockIdx.x * blockDim.x + threadIdx.x;
    int stride = gridDim.x * blockDim.x;
    for (; i < n4; i += stride)
        out[i] = transform4(x[i]);
}

__global__ void ew_scalar_tail(const float* __restrict__ x,
                               float* __restrict__ out, int start, int n) {
    int i = start + blockIdx.x * blockDim.x + threadIdx.x;
    if (i < n) {
        const float c = 2.0f / 3.0f;
        float r = fmaf(x[i], c, c);
        if (r > 0.0f) r -= 5.0f;
        out[i] = r;
    }
}

extern "C" void kernel_launch(void* const* d_in, const int* in_sizes, int n_in,
                              void* d_out, int out_size) {
    const float* x = (const float*)d_in[0];
    float* out = (float*)d_out;
    int n = in_sizes[0];          // 67,108,864
    int n4 = n >> 2;              // 16,777,216 = 2^24

    const int threads = 256;
    const int blocks = 1024;      // 2^18 threads total
    const long long chunk = (long long)4 * threads * blocks;  // 2^20

    if ((n % 4) == 0 && (n4 % chunk) == 0) {
        ew_loop4<<<blocks, threads>>>((const float4*)x, (float4*)out, n4);
    } else {
        int n4f = n >> 2;
        if (n4f > 0) {
            int b = (n4f + threads * 8 - 1) / (threads * 8);
            ew_gs<<<b, threads>>>((const float4*)x, (float4*)out, n4f);
        }
        int tail = n - (n4f << 2);
        if (tail > 0)
            ew_scalar_tail<<<(tail + 255) / 256, 256>>>(x, out, n4f << 2, n);
    }
}

// round 4
// speedup vs baseline: 1.1118x; 1.1118x over previous
#include <cuda_runtime.h>
#include <cuda_bf16.h>

// Elementwise: y = (x + 1) * 2 / 3; if (y > 0) y -= 5;
// 8192*8192 fp32 = 67,108,864 elements (2^24 float4s). HBM-streaming.
//
// Best-measured geometry (R0): 8192 blocks x 256 threads, grid-stride,
// 8 float4/thread. Micro-tweaks: unroll-by-2 paired loads, __ldcg
// (L2-only, skip L1 allocate for single-use data). Default stores.

__device__ __forceinline__ float4 transform4(float4 v) {
    const float c = 2.0f / 3.0f;   // (x+1)*2/3 == fma(x, 2/3, 2/3)
    float4 r;
    r.x = fmaf(v.x, c, c);
    r.y = fmaf(v.y, c, c);
    r.z = fmaf(v.z, c, c);
    r.w = fmaf(v.w, c, c);
    if (r.x > 0.0f) r.x -= 5.0f;
    if (r.y > 0.0f) r.y -= 5.0f;
    if (r.z > 0.0f) r.z -= 5.0f;
    if (r.w > 0.0f) r.w -= 5.0f;
    return r;
}

// Requires n4 % (2 * gridDim.x * blockDim.x) == 0 on the fast path.
__global__ __launch_bounds__(256) void ew_kernel(const float4* __restrict__ x,
                                                 float4* __restrict__ out,
                                                 int n4) {
    const int T = gridDim.x * blockDim.x;
    int i = blockIdx.x * blockDim.x + threadIdx.x;
    const int step = 2 * T;
    for (; i < n4; i += step) {
        // Paired independent loads (MLP=2), L2-only cache policy.
        float4 v0 = __ldcg(x + i);
        float4 v1 = __ldcg(x + i + T);
        out[i]     = transform4(v0);
        out[i + T] = transform4(v1);
    }
}

// Fallback grid-stride for arbitrary sizes.
__global__ __launch_bounds__(256) void ew_gs(const float4* __restrict__ x,
                                             float4* __restrict__ out, int n4) {
    int i = blockIdx.x * blockDim.x + threadIdx.x;
    int stride = gridDim.x * blockDim.x;
    for (; i < n4; i += stride)
        out[i] = transform4(x[i]);
}

__global__ void ew_scalar_tail(const float* __restrict__ x,
                               float* __restrict__ out, int start, int n) {
    int i = start + blockIdx.x * blockDim.x + threadIdx.x;
    if (i < n) {
        const float c = 2.0f / 3.0f;
        float r = fmaf(x[i], c, c);
        if (r > 0.0f) r -= 5.0f;
        out[i] = r;
    }
}

extern "C" void kernel_launch(void* const* d_in, const int* in_sizes, int n_in,
                              void* d_out, int out_size) {
    const float* x = (const float*)d_in[0];
    float* out = (float*)d_out;
    int n = in_sizes[0];          // 67,108,864
    int n4 = n >> 2;              // 16,777,216 = 2^24

    const int threads = 256;
    const int blocks = 8192;      // proven-best geometry (R0)
    const long long chunk = (long long)2 * threads * blocks;  // 2^22

    if ((n % 4) == 0 && ((long long)n4 % chunk) == 0) {
        ew_kernel<<<blocks, threads>>>((const float4*)x, (float4*)out, n4);
    } else {
        int n4f = n >> 2;
        if (n4f > 0) {
            int b = (n4f + threads * 8 - 1) / (threads * 8);
            ew_gs<<<b, threads>>>((const float4*)x, (float4*)out, n4f);
        }
        int tail = n - (n4f << 2);
        if (tail > 0)
            ew_scalar_tail<<<(tail + 255) / 256, 256>>>(x, out, n4f << 2, n);
    }
}

// round 5
// speedup vs baseline: 1.1204x; 1.0077x over previous
#include <cuda_runtime.h>
#include <cuda_bf16.h>

// Elementwise: y = (x + 1) * 2 / 3; if (y > 0) y -= 5;
// 8192*8192 fp32 = 67,108,864 elements (2^24 float4s). HBM-streaming.
//
// R4: flat loop-free kernel (16384 blocks x 256 threads, 4 float4/thread --
// lowest wallclock replay gap, per R1) + __ldcg L2-only loads (highest
// DRAM%, per R3). Default stores.

__device__ __forceinline__ float4 transform4(float4 v) {
    const float c = 2.0f / 3.0f;   // (x+1)*2/3 == fma(x, 2/3, 2/3)
    float4 r;
    r.x = fmaf(v.x, c, c);
    r.y = fmaf(v.y, c, c);
    r.z = fmaf(v.z, c, c);
    r.w = fmaf(v.w, c, c);
    if (r.x > 0.0f) r.x -= 5.0f;
    if (r.y > 0.0f) r.y -= 5.0f;
    if (r.z > 0.0f) r.z -= 5.0f;
    if (r.w > 0.0f) r.w -= 5.0f;
    return r;
}

// Each block handles 256 threads * 4 float4 = 1024 float4s. No bounds checks;
// launcher guarantees exact divisibility on the fast path.
__global__ __launch_bounds__(256) void ew_flat4(const float4* __restrict__ x,
                                                float4* __restrict__ out) {
    int base = blockIdx.x * (256 * 4) + threadIdx.x;
    float4 v0 = __ldcg(x + base + 0 * 256);
    float4 v1 = __ldcg(x + base + 1 * 256);
    float4 v2 = __ldcg(x + base + 2 * 256);
    float4 v3 = __ldcg(x + base + 3 * 256);
    out[base + 0 * 256] = transform4(v0);
    out[base + 1 * 256] = transform4(v1);
    out[base + 2 * 256] = transform4(v2);
    out[base + 3 * 256] = transform4(v3);
}

// Fallback grid-stride for arbitrary sizes.
__global__ __launch_bounds__(256) void ew_gs(const float4* __restrict__ x,
                                             float4* __restrict__ out, int n4) {
    int i = blockIdx.x * blockDim.x + threadIdx.x;
    int stride = gridDim.x * blockDim.x;
    for (; i < n4; i += stride)
        out[i] = transform4(__ldcg(x + i));
}

__global__ void ew_scalar_tail(const float* __restrict__ x,
                               float* __restrict__ out, int start, int n) {
    int i = start + blockIdx.x * blockDim.x + threadIdx.x;
    if (i < n) {
        const float c = 2.0f / 3.0f;
        float r = fmaf(x[i], c, c);
        if (r > 0.0f) r -= 5.0f;
        out[i] = r;
    }
}

extern "C" void kernel_launch(void* const* d_in, const int* in_sizes, int n_in,
                              void* d_out, int out_size) {
    const float* x = (const float*)d_in[0];
    float* out = (float*)d_out;
    int n = in_sizes[0];          // 67,108,864
    int n4 = n >> 2;              // 16,777,216 = 2^24

    const int per_block = 256 * 4;  // 1024 float4s per block
    if ((n % 4) == 0 && (n4 % per_block) == 0) {
        int blocks = n4 / per_block;  // 16384
        ew_flat4<<<blocks, 256>>>((const float4*)x, (float4*)out);
    } else {
        int n4f = n >> 2;
        if (n4f > 0) {
            int b = (n4f + 256 * 8 - 1) / (256 * 8);
            ew_gs<<<b, 256>>>((const float4*)x, (float4*)out, n4f);
        }
        int tail = n - (n4f << 2);
        if (tail > 0)
            ew_scalar_tail<<<(tail + 255) / 256, 256>>>(x, out, n4f << 2, n);
    }
}

// round 6
// speedup vs baseline: 1.1238x; 1.0031x over previous
#include <cuda_runtime.h>
#include <cuda_bf16.h>

// Elementwise: y = (x + 1) * 2 / 3; if (y > 0) y -= 5;
// 8192*8192 fp32 = 67,108,864 elements (2^24 float4s). HBM-streaming.
//
// R5: flat loop-free kernel, 8192 blocks x 256 threads, 8 float4/thread in
// two front-batched groups of 4 independent __ldcg (L2-only) loads.
// Wallclock is pinned at total-DRAM-traffic / sustained-BW (~82.7us);
// this variant minimizes SM-side overhead at that ceiling.

__device__ __forceinline__ float4 transform4(float4 v) {
    const float c = 2.0f / 3.0f;   // (x+1)*2/3 == fma(x, 2/3, 2/3)
    float4 r;
    r.x = fmaf(v.x, c, c);
    r.y = fmaf(v.y, c, c);
    r.z = fmaf(v.z, c, c);
    r.w = fmaf(v.w, c, c);
    if (r.x > 0.0f) r.x -= 5.0f;
    if (r.y > 0.0f) r.y -= 5.0f;
    if (r.z > 0.0f) r.z -= 5.0f;
    if (r.w > 0.0f) r.w -= 5.0f;
    return r;
}

// Each block handles 256 threads * 8 float4 = 2048 float4s. No bounds checks;
// launcher guarantees exact divisibility on the fast path.
__global__ __launch_bounds__(256) void ew_flat8(const float4* __restrict__ x,
                                                float4* __restrict__ out) {
    int base = blockIdx.x * (256 * 8) + threadIdx.x;

    float4 v0 = __ldcg(x + base + 0 * 256);
    float4 v1 = __ldcg(x + base + 1 * 256);
    float4 v2 = __ldcg(x + base + 2 * 256);
    float4 v3 = __ldcg(x + base + 3 * 256);
    out[base + 0 * 256] = transform4(v0);
    out[base + 1 * 256] = transform4(v1);
    out[base + 2 * 256] = transform4(v2);
    out[base + 3 * 256] = transform4(v3);

    float4 v4 = __ldcg(x + base + 4 * 256);
    float4 v5 = __ldcg(x + base + 5 * 256);
    float4 v6 = __ldcg(x + base + 6 * 256);
    float4 v7 = __ldcg(x + base + 7 * 256);
    out[base + 4 * 256] = transform4(v4);
    out[base + 5 * 256] = transform4(v5);
    out[base + 6 * 256] = transform4(v6);
    out[base + 7 * 256] = transform4(v7);
}

// Fallback grid-stride for arbitrary sizes.
__global__ __launch_bounds__(256) void ew_gs(const float4* __restrict__ x,
                                             float4* __restrict__ out, int n4) {
    int i = blockIdx.x * blockDim.x + threadIdx.x;
    int stride = gridDim.x * blockDim.x;
    for (; i < n4; i += stride)
        out[i] = transform4(__ldcg(x + i));
}

__global__ void ew_scalar_tail(const float* __restrict__ x,
                               float* __restrict__ out, int start, int n) {
    int i = start + blockIdx.x * blockDim.x + threadIdx.x;
    if (i < n) {
        const float c = 2.0f / 3.0f;
        float r = fmaf(x[i], c, c);
        if (r > 0.0f) r -= 5.0f;
        out[i] = r;
    }
}

extern "C" void kernel_launch(void* const* d_in, const int* in_sizes, int n_in,
                              void* d_out, int out_size) {
    const float* x = (const float*)d_in[0];
    float* out = (float*)d_out;
    int n = in_sizes[0];          // 67,108,864
    int n4 = n >> 2;              // 16,777,216 = 2^24

    const int per_block = 256 * 8;  // 2048 float4s per block
    if ((n % 4) == 0 && (n4 % per_block) == 0) {
        int blocks = n4 / per_block;  // 8192
        ew_flat8<<<blocks, 256>>>((const float4*)x, (float4*)out);
    } else {
        int n4f = n >> 2;
        if (n4f > 0) {
            int b = (n4f + 256 * 8 - 1) / (256 * 8);
            ew_gs<<<b, 256>>>((const float4*)x, (float4*)out, n4f);
        }
        int tail = n - (n4f << 2);
        if (tail > 0)
            ew_scalar_tail<<<(tail + 255) / 256, 256>>>(x, out, n4f << 2, n);
    }
}